// round 7
// baseline (speedup 1.0000x reference)
#include <cuda_runtime.h>
#include <cuda_fp16.h>
#include <cstdint>

// ===================== problem constants =====================
#define BATCH_ 8192
#define O_     8
#define K_     2048      // N*U
#define V_     256

// ===================== GEMM tiling =====================
#define BM 128
#define BN 128
#define BK 32
#define NSTG 4
#define ROWB 80          // padded smem row: 32 halves + 16B pad
#define A_BYTES (BM * ROWB)            // 10240
#define B_BYTES (BN * ROWB)            // 10240
#define STG_BYTES (A_BYTES + B_BYTES)  // 20480
#define SMEM_TOTAL (NSTG * STG_BYTES)  // 81920

// ===================== scratch =====================
__device__ __half g_xh[(size_t)BATCH_ * K_];   // fp16 X (active n-slices only)
__device__ __half g_wh[(size_t)O_ * V_ * K_];  // gated, transposed fp16 W [o][v][k]
__device__ float  g_z[64];
__device__ int    g_nlist[O_ * 8];
__device__ int    g_ncnt[O_];
__device__ int    g_unlist[8];                 // union of active n over all o
__device__ int    g_uncnt;

// ===================== helpers =====================
__device__ __forceinline__ uint32_t smem_u32(const void* p) {
    uint32_t a;
    asm("{ .reg .u64 t; cvta.to.shared.u64 t, %1; cvt.u32.u64 %0, t; }" : "=r"(a) : "l"(p));
    return a;
}
__device__ __forceinline__ void cpa16(uint32_t d, const void* g) {
    asm volatile("cp.async.cg.shared.global [%0], [%1], 16;" :: "r"(d), "l"(g));
}
#define CP_COMMIT() asm volatile("cp.async.commit_group;" ::: "memory")
#define CP_WAIT2()  asm volatile("cp.async.wait_group 2;" ::: "memory")

__device__ __forceinline__ void ldsm4(uint32_t (&r)[4], uint32_t addr) {
    asm volatile("ldmatrix.sync.aligned.m8n8.x4.shared.b16 {%0,%1,%2,%3}, [%4];"
                 : "=r"(r[0]), "=r"(r[1]), "=r"(r[2]), "=r"(r[3]) : "r"(addr));
}
__device__ __forceinline__ void mma16816(float* c, const uint32_t* a,
                                         uint32_t b0, uint32_t b1) {
    asm volatile(
        "mma.sync.aligned.m16n8k16.row.col.f32.f16.f16.f32 "
        "{%0,%1,%2,%3}, {%4,%5,%6,%7}, {%8,%9}, {%0,%1,%2,%3};"
        : "+f"(c[0]), "+f"(c[1]), "+f"(c[2]), "+f"(c[3])
        : "r"(a[0]), "r"(a[1]), "r"(a[2]), "r"(a[3]), "r"(b0), "r"(b1));
}

__device__ __forceinline__ float gate_z(const float* u_param, const float* alpha, int idx) {
    float uu = u_param[idx];
    float s = __logf(uu) - __logf(1.0f - uu) + __logf(alpha[0]) * (1.0f / 0.9f);
    s = 1.0f / (1.0f + __expf(-s));
    float z = s * 1.2f - 0.1f;
    return fminf(fmaxf(z, 0.0f), 1.0f);
}

// ===================== kernel 0: gates (1 block, 64 threads) =====================
__global__ void gates(const float* __restrict__ alpha,
                      const float* __restrict__ u_param) {
    __shared__ float zs[64];
    int t = threadIdx.x;
    float z = gate_z(u_param, alpha, t);
    zs[t] = z;
    g_z[t] = z;
    __syncthreads();
    if (t < 8) {                       // per-o compacted n list
        int cnt = 0;
        for (int nn = 0; nn < 8; nn++)
            if (zs[t * 8 + nn] > 0.0f) g_nlist[t * 8 + cnt++] = nn;
        g_ncnt[t] = cnt;
    }
    if (t == 8) {                      // union active-n list
        int cnt = 0;
        for (int nn = 0; nn < 8; nn++) {
            int a = 0;
            for (int o = 0; o < 8; o++) a |= (zs[o * 8 + nn] > 0.0f);
            if (a) g_unlist[cnt++] = nn;
        }
        g_uncnt = cnt;
    }
}

// ===================== kernel 1: prepass =====================
// blocks [0, 2048): X -> fp16, loops over active-n union only (4 b-rows/block).
// blocks [2048, 3072): gate-scaled transpose of W for open gates.
__global__ void prep(const float* __restrict__ X,
                     const float* __restrict__ T) {
    int tid = threadIdx.x;

    if (blockIdx.x < 2048) {
        __shared__ int un[8];
        __shared__ int uc;
        if (tid < 8) un[tid] = g_unlist[tid];
        if (tid == 8) uc = g_uncnt;
        __syncthreads();

        int b  = (blockIdx.x << 2) + (tid >> 6);   // 4 b-rows per block
        int u4 = tid & 63;
        for (int j = 0; j < uc; j++) {
            int n = un[j];
            size_t e = ((size_t)b * 8 + n) * 256 + u4 * 4;
            float4 v = *reinterpret_cast<const float4*>(X + e);
            __half2 h0 = __floats2half2_rn(v.x, v.y);
            __half2 h1 = __floats2half2_rn(v.z, v.w);
            uint2 w;
            w.x = *reinterpret_cast<uint32_t*>(&h0);
            w.y = *reinterpret_cast<uint32_t*>(&h1);
            *reinterpret_cast<uint2*>(g_xh + e) = w;
        }
        return;
    }

    __shared__ float tile[64][65];
    __shared__ float zsh;
    int blk = blockIdx.x - 2048;      // 0..1023
    int on = blk >> 4;
    int o = on >> 3, n = on & 7;
    int u0 = ((blk >> 2) & 3) * 64;
    int v0 = (blk & 3) * 64;

    if (tid == 0) zsh = g_z[o * 8 + n];
    __syncthreads();
    float z = zsh;
    if (z == 0.0f) return;

    const float* tb = T + (((size_t)(o * 8 + n) * 256 + u0) * 256 + v0);
#pragma unroll
    for (int i = 0; i < 16; i++) {
        int r = i * 4 + (tid >> 6);
        int c = tid & 63;
        tile[r][c] = tb[(size_t)r * 256 + c];
    }
    __syncthreads();

    __half* wb = g_wh + ((size_t)o * 256 + v0) * 2048 + n * 256 + u0;
#pragma unroll
    for (int i = 0; i < 16; i++) {
        int r = i * 4 + (tid >> 6);   // v-row
        int c = tid & 63;             // u-col (k contiguous)
        wb[(size_t)r * 2048 + c] = __float2half_rn(tile[c][r] * z);
    }
}

// ===================== fp16 pipelined GEMM with gate skipping =====================
// Grid (16, 64): x = (o, n-half)  [spreads active o over consecutive block IDs],
//                y = m-tile. 256 threads = 8 warps (4m x 2n).
__global__ __launch_bounds__(256)
void gemm_fp16(float* __restrict__ out) {
    extern __shared__ char smem[];
    const uint32_t sb = smem_u32(smem);
    __shared__ int nlist_s[8];
    __shared__ int cnt_s;

    const int tid = threadIdx.x, lane = tid & 31, warp = tid >> 5;
    const int o  = blockIdx.x >> 1;
    const int n0 = (blockIdx.x & 1) * BN;
    const int m0 = blockIdx.y * BM;

    if (tid < 8) nlist_s[tid] = g_nlist[o * 8 + tid];
    if (tid == 8) cnt_s = g_ncnt[o];
    __syncthreads();
    const int chunks = cnt_s * 8;

    // ---- fast path: closed o -> coalesced write-through zeros ----
    if (chunks == 0) {
        float* base = out + ((size_t)m0 * O_ + o) * V_ + n0;
        const uint4 z4 = make_uint4(0u, 0u, 0u, 0u);
#pragma unroll
        for (int i = tid; i < 4096; i += 256) {       // 128 rows x 32 uint4
            int r = i >> 5, c = i & 31;
            __stwt(reinterpret_cast<uint4*>(base + (size_t)r * (O_ * V_)) + c, z4);
        }
        return;
    }

    const __half* Ag = g_xh + (size_t)m0 * K_;
    const __half* Bg = g_wh + ((size_t)o * V_ + n0) * K_;

    const int i0 = tid * 2;
    const int r0 = i0 >> 2, c0 = i0 & 3;
    const int r1 = (i0 + 1) >> 2, c1 = (i0 + 1) & 3;

    auto issue = [&](int c) {
        const uint32_t so = (uint32_t)(c & 3) * STG_BYTES;
        const int k0 = (nlist_s[c >> 3] << 8) + ((c & 7) << 5);
        cpa16(sb + so + r0 * ROWB + c0 * 16,           Ag + (size_t)r0 * K_ + k0 + c0 * 8);
        cpa16(sb + so + r1 * ROWB + c1 * 16,           Ag + (size_t)r1 * K_ + k0 + c1 * 8);
        cpa16(sb + so + A_BYTES + r0 * ROWB + c0 * 16, Bg + (size_t)r0 * K_ + k0 + c0 * 8);
        cpa16(sb + so + A_BYTES + r1 * ROWB + c1 * 16, Bg + (size_t)r1 * K_ + k0 + c1 * 8);
    };

    const int mo = (warp >> 1) * 32;
    const int no = (warp & 1) * 64;
    uint32_t a_addr[2], b_addr[4];
    {
        const int arl = lane & 15;
        const int akh = (lane >> 4) & 1;
#pragma unroll
        for (int mf = 0; mf < 2; mf++)
            a_addr[mf] = sb + (mo + mf * 16 + arl) * ROWB + akh * 16;
        const int brl = (lane & 7) + ((lane >> 4) & 1) * 8;
        const int bkh = (lane >> 3) & 1;
#pragma unroll
        for (int p = 0; p < 4; p++)
            b_addr[p] = sb + A_BYTES + (no + p * 16 + brl) * ROWB + bkh * 16;
    }

    float acc[2][8][4];
#pragma unroll
    for (int i = 0; i < 2; i++)
#pragma unroll
        for (int j = 0; j < 8; j++)
#pragma unroll
            for (int k = 0; k < 4; k++) acc[i][j][k] = 0.0f;

#pragma unroll
    for (int p = 0; p < 3; p++) {
        if (p < chunks) issue(p);
        CP_COMMIT();
    }

    for (int c = 0; c < chunks; ++c) {
        CP_WAIT2();
        __syncthreads();
        if (c + 3 < chunks) issue(c + 3);
        CP_COMMIT();

        const uint32_t so = (uint32_t)(c & 3) * STG_BYTES;
#pragma unroll
        for (int ks = 0; ks < 2; ks++) {
            const uint32_t kb = so + ks * 32;
            uint32_t a[2][4], b[4][4];
#pragma unroll
            for (int mf = 0; mf < 2; mf++) ldsm4(a[mf], a_addr[mf] + kb);
#pragma unroll
            for (int p = 0; p < 4; p++) ldsm4(b[p], b_addr[p] + kb);
#pragma unroll
            for (int mf = 0; mf < 2; mf++)
#pragma unroll
                for (int p = 0; p < 4; p++) {
                    mma16816(acc[mf][2 * p],     a[mf], b[p][0], b[p][1]);
                    mma16816(acc[mf][2 * p + 1], a[mf], b[p][2], b[p][3]);
                }
        }
        __syncthreads();
    }

    const int gid = lane >> 2, tig = lane & 3;
#pragma unroll
    for (int mf = 0; mf < 2; mf++) {
        const int brow = m0 + mo + mf * 16 + gid;
#pragma unroll
        for (int nb = 0; nb < 8; nb++) {
            const int v = n0 + no + nb * 8 + tig * 2;
            float* c = acc[mf][nb];
            __stwt(reinterpret_cast<float2*>(
                out + ((size_t)brow * O_ + o) * V_ + v), make_float2(c[0], c[1]));
            __stwt(reinterpret_cast<float2*>(
                out + ((size_t)(brow + 8) * O_ + o) * V_ + v), make_float2(c[2], c[3]));
        }
    }
}

// ===================== host =====================
extern "C" void kernel_launch(void* const* d_in, const int* in_sizes, int n_in,
                              void* d_out, int out_size) {
    const float* x = nullptr, *alpha = nullptr, *u = nullptr, *T = nullptr;
    for (int i = 0; i < n_in; i++) {
        switch (in_sizes[i]) {
            case 16777216: x     = (const float*)d_in[i]; break;
            case 1:        alpha = (const float*)d_in[i]; break;
            case 64:       u     = (const float*)d_in[i]; break;
            case 4194304:  T     = (const float*)d_in[i]; break;
        }
    }
    if (!x || !alpha || !u || !T) return;
    float* out = (float*)d_out;

    static bool attr_set = false;
    if (!attr_set) {
        cudaFuncSetAttribute(gemm_fp16, cudaFuncAttributeMaxDynamicSharedMemorySize,
                             SMEM_TOTAL);
        attr_set = true;
    }

    gates<<<1, 64>>>(alpha, u);
    prep<<<2048 + 1024, 256>>>(x, T);
    gemm_fp16<<<dim3(16, 64), 256, SMEM_TOTAL>>>(out);
}